// round 14
// baseline (speedup 1.0000x reference)
#include <cuda_runtime.h>
#include <cuda_fp16.h>
#include <stdint.h>
#include <math.h>

#define NE 50000
#define HD 256
#define KD 768
#define KB2 320   // phase-2 K padded: 256 he + 32 q + 32 zero-pad (5 chunks of 64)
#define NC1 12    // phase-1 K chunks of 64
#define NC2 5     // phase-2 K chunks of 64

// SMEM layout (halves)
#define A2_STRIDE 328                            // 656 B row stride: 656%128=16 -> conflict-free
#define A2_HALVES (128 * A2_STRIDE)              // 41984
#define S0 A2_HALVES                             // staging base (halves)
#define ST_ROW 72                                // staged row stride (64 + 8 pad): 144B, conflict-free
#define A_STG (128 * ST_ROW)                     // 9216 halves
#define B_STG (256 * ST_ROW)                     // 18432 halves
#define STAGE (A_STG + B_STG)                    // 27648 halves per stage
#define KAN_OFF (S0 + 2 * STAGE)                 // 97280 halves = 194560 B
#define KAN_FLOATS 4608
#define SMEM_BYTES (KAN_OFF * 2 + KAN_FLOATS * 4)  // 212992

// ---------------- scratch ----------------------------------------------------
__device__ __half g_WeH[HD * KD];          // W_e fp16 [n][k] k<768
__device__ __half g_WcH[HD * KB2];         // W' fp16 [n][k] k<320 (zeros >=267)
__device__ float g_bias2[HD];
__device__ float g_sum8[NE * 8];
__device__ float g_sum1[NE];
__device__ int   g_cnt_ue[NE];
__device__ int   g_cnt_se[NE];

// ---------------- weight prep (+ accumulator zeroing, fused) ----------------
__global__ void prep_kernel(const float* __restrict__ W_e,
                            const float* __restrict__ Wr_ue, const float* __restrict__ Wr_se,
                            const float* __restrict__ bl_ue, const float* __restrict__ bl_se) {
    int idx = blockIdx.x * 256 + threadIdx.x;   // 196608 threads
    for (int j = idx; j < NE * 8; j += 196608) g_sum8[j] = 0.f;
    if (idx < NE) { g_sum1[idx] = 0.f; g_cnt_ue[idx] = 0; g_cnt_se[idx] = 0; }
    if (idx < HD) g_bias2[idx] = bl_ue[idx] + bl_se[idx];
    g_WeH[idx] = __float2half_rn(W_e[idx]);
    if (idx < HD * HD) {
        int n = idx >> 8, k = idx & 255;
        g_WcH[n * KB2 + k] = __float2half_rn(Wr_ue[idx] + Wr_se[idx]);
    }
}

// ---------------- prep2: rank-11 correction cols + zero pad (k=256..319) ----
__global__ void prep2_kernel(const float* __restrict__ Wl_ue, const float* __restrict__ W_u,
                             const float* __restrict__ b_u,
                             const float* __restrict__ Wl_se, const float* __restrict__ W_s,
                             const float* __restrict__ b_s) {
    int n = blockIdx.x;
    int c = threadIdx.x;    // 0..63
    float acc = 0.f;
    if (c < 8) {
        for (int h = 0; h < HD; h++) acc += Wl_ue[n * HD + h] * W_u[h * 8 + c];
    } else if (c == 8) {
        for (int h = 0; h < HD; h++) acc += Wl_ue[n * HD + h] * b_u[h];
    } else if (c == 9) {
        for (int h = 0; h < HD; h++) acc += Wl_se[n * HD + h] * W_s[h];
    } else if (c == 10) {
        for (int h = 0; h < HD; h++) acc += Wl_se[n * HD + h] * b_s[h];
    }
    g_WcH[n * KB2 + 256 + c] = __float2half_rn(acc);
}

// ---------------- merged edge aggregation -----------------------------------
__global__ void agg_kernel(const int* __restrict__ ue_src, const int* __restrict__ ue_dst,
                           const float* __restrict__ x_url, int n_ue,
                           const int* __restrict__ se_src, const int* __restrict__ se_dst,
                           const float* __restrict__ x_sender, int n_se) {
    int e = blockIdx.x * blockDim.x + threadIdx.x;
    if (e < n_ue) {
        int s = ue_src[e], d = ue_dst[e];
        const float4* xu = (const float4*)(x_url + (size_t)s * 8);
        float4 a = xu[0], b = xu[1];
        float* p = g_sum8 + (size_t)d * 8;
        asm volatile("red.global.add.v4.f32 [%0], {%1,%2,%3,%4};"
                     :: "l"(p), "f"(a.x), "f"(a.y), "f"(a.z), "f"(a.w) : "memory");
        asm volatile("red.global.add.v4.f32 [%0], {%1,%2,%3,%4};"
                     :: "l"(p + 4), "f"(b.x), "f"(b.y), "f"(b.z), "f"(b.w) : "memory");
        asm volatile("red.global.add.s32 [%0], %1;" :: "l"(g_cnt_ue + d), "r"(1) : "memory");
    } else {
        int e2 = e - n_ue;
        if (e2 < n_se) {
            int d = se_dst[e2];
            float v = x_sender[se_src[e2]];
            asm volatile("red.global.add.f32 [%0], %1;" :: "l"(g_sum1 + d), "f"(v) : "memory");
            asm volatile("red.global.add.s32 [%0], %1;" :: "l"(g_cnt_se + d), "r"(1) : "memory");
        }
    }
}

// ---------------- helpers -----------------------------------------------------
__device__ __forceinline__ void cp16(uint32_t d, const void* s) {
    asm volatile("cp.async.cg.shared.global [%0], [%1], 16;" :: "r"(d), "l"(s));
}
#define CP_COMMIT() asm volatile("cp.async.commit_group;")
#define CP_WAIT0()  asm volatile("cp.async.wait_group 0;")

__device__ __forceinline__ void ldsm4(uint32_t addr, uint32_t& r0, uint32_t& r1,
                                      uint32_t& r2, uint32_t& r3) {
    asm volatile("ldmatrix.sync.aligned.m8n8.x4.shared.b16 {%0,%1,%2,%3}, [%4];"
                 : "=r"(r0), "=r"(r1), "=r"(r2), "=r"(r3) : "r"(addr));
}

__device__ __forceinline__ void mma16816(float* c, const uint32_t* a, uint32_t b0, uint32_t b1) {
    asm volatile("mma.sync.aligned.m16n8k16.row.col.f32.f16.f16.f32 "
                 "{%0,%1,%2,%3}, {%4,%5,%6,%7}, {%8,%9}, {%0,%1,%2,%3};"
                 : "+f"(c[0]), "+f"(c[1]), "+f"(c[2]), "+f"(c[3])
                 : "r"(a[0]), "r"(a[1]), "r"(a[2]), "r"(a[3]), "r"(b0), "r"(b1));
}

// ---------------- fully fused: proj + conv + activation + KAN ---------------
// 1024 threads, 32 warps (4m x 8n), warp tile 32x32, block tile 128x256.
// K-chunk 64: phase 1 = 12 iterations, phase 2 = 5 (KB2=320 padded).
__global__ __launch_bounds__(1024, 1) void fused_gemm(const float* __restrict__ x_email,
                                                      const float* __restrict__ b_e,
                                                      const float* __restrict__ gate,
                                                      const float* __restrict__ base_w,
                                                      const float* __restrict__ spline_w,
                                                      float* __restrict__ out) {
    extern __shared__ __half dsm[];
    const uint32_t sbase = (uint32_t)__cvta_generic_to_shared(dsm);
    __half* A2 = dsm;
    float* kanw = (float*)(dsm + KAN_OFF);

    const int tid = threadIdx.x;
    const int lane = tid & 31;
    const int warp = tid >> 5;      // 0..31
    const int wm = warp & 3;        // 4 m-slabs of 32
    const int wn = warp >> 2;       // 8 n-slabs of 32
    const int m0 = blockIdx.x * 128;

    const int a_row_off = ((lane >> 3) & 1) * 8 + (lane & 7);
    const int a_k_off   = ((lane >> 4) & 1) * 8;
    const int b_row_off = ((lane >> 4) & 1) * 8 + (lane & 7);
    const int b_k_off   = ((lane >> 3) & 1) * 8;
    const int g = lane >> 2, t = lane & 3;

    // ---- KAN weight load ----
    for (int i = tid; i < 512; i += 1024) kanw[i] = base_w[i];
    for (int i = tid; i < 4096; i += 1024) {
        int o = i >> 11;
        int h = (i >> 3) & 255;
        int gg = i & 7;
        kanw[512 + gg * 512 + o * 256 + h] = spline_w[i];
    }

    float C[2][4][4];
#pragma unroll
    for (int i = 0; i < 2; i++)
#pragma unroll
        for (int j = 0; j < 4; j++)
#pragma unroll
            for (int q = 0; q < 4; q++) C[i][j][q] = 0.f;

    float4 Ar[2];

    // ================= PHASE 1: K = 768, chunks of 64 =================
    auto issueB1 = [&](int c, int buf) {
        const int k0 = c * 64;
        uint32_t bh = sbase + (uint32_t)(S0 + buf * STAGE + A_STG) * 2u;
#pragma unroll
        for (int i = 0; i < 2; i++) {
            int f = tid + i * 1024;          // 256 rows x 8 chunks of 16B
            int row = f >> 3, m = f & 7;
            cp16(bh + (uint32_t)(row * ST_ROW + m * 8) * 2,
                 g_WeH + (size_t)row * KD + k0 + m * 8);
        }
        CP_COMMIT();
    };
    auto loadA1 = [&](int c) {
        const int k0 = c * 64;
        int row = tid >> 3, seg = tid & 7;   // 128 rows x 8 segs of 8 fp32
        int gr = m0 + row;
        if (gr < NE) {
            const float4* p = (const float4*)(x_email + (size_t)gr * KD + k0 + seg * 8);
            Ar[0] = p[0]; Ar[1] = p[1];
        } else {
            Ar[0] = Ar[1] = make_float4(0.f, 0.f, 0.f, 0.f);
        }
    };
    auto storeA1 = [&](int buf) {
        __half* Ah = dsm + S0 + buf * STAGE;
        int row = tid >> 3, seg = tid & 7;
        __half2 h0 = __floats2half2_rn(Ar[0].x, Ar[0].y);
        __half2 h1 = __floats2half2_rn(Ar[0].z, Ar[0].w);
        __half2 h2 = __floats2half2_rn(Ar[1].x, Ar[1].y);
        __half2 h3 = __floats2half2_rn(Ar[1].z, Ar[1].w);
        uint4 q;
        q.x = *(uint32_t*)&h0; q.y = *(uint32_t*)&h1;
        q.z = *(uint32_t*)&h2; q.w = *(uint32_t*)&h3;
        *(uint4*)(Ah + row * ST_ROW + seg * 8) = q;
    };

    loadA1(0);
    issueB1(0, 0);

    for (int kt = 0; kt < NC1; kt++) {
        const int cur = kt & 1;
        storeA1(cur);
        CP_WAIT0();
        __syncthreads();
        if (kt + 1 < NC1) {
            issueB1(kt + 1, cur ^ 1);
            loadA1(kt + 1);
        }
        const uint32_t sAh = sbase + (uint32_t)(S0 + cur * STAGE) * 2u;
        const uint32_t sBh = sbase + (uint32_t)(S0 + cur * STAGE + A_STG) * 2u;
#pragma unroll
        for (int kh = 0; kh < 4; kh++) {
            uint32_t Af[2][4];
#pragma unroll
            for (int mf = 0; mf < 2; mf++) {
                int row = wm * 32 + mf * 16 + a_row_off;
                uint32_t off = (uint32_t)(row * ST_ROW + kh * 16 + a_k_off) * 2;
                ldsm4(sAh + off, Af[mf][0], Af[mf][1], Af[mf][2], Af[mf][3]);
            }
            uint32_t Bf[2][4];
#pragma unroll
            for (int nf = 0; nf < 2; nf++) {
                int row = wn * 32 + nf * 16 + b_row_off;
                uint32_t off = (uint32_t)(row * ST_ROW + kh * 16 + b_k_off) * 2;
                ldsm4(sBh + off, Bf[nf][0], Bf[nf][1], Bf[nf][2], Bf[nf][3]);
            }
#pragma unroll
            for (int mf = 0; mf < 2; mf++) {
#pragma unroll
                for (int j = 0; j < 4; j++) {
                    int nf = j >> 1;
                    int hh = j & 1;
                    mma16816(C[mf][j], Af[mf], Bf[nf][hh * 2], Bf[nf][hh * 2 + 1]);
                }
            }
        }
    }

    // ---- epilogue 1: he_pre + b_e -> fp16 A2 cols 0..255
#pragma unroll
    for (int mf = 0; mf < 2; mf++) {
        int rl0 = wm * 32 + mf * 16 + g;
#pragma unroll
        for (int j = 0; j < 4; j++) {
            int col = wn * 32 + j * 8 + t * 2;
            float b0 = b_e[col], b1 = b_e[col + 1];
#pragma unroll
            for (int half = 0; half < 2; half++) {
                int rl = rl0 + half * 8;
                __half2 hp;
                hp.x = __float2half_rn(C[mf][j][half * 2 + 0] + b0);
                hp.y = __float2half_rn(C[mf][j][half * 2 + 1] + b1);
                *(__half2*)&A2[rl * A2_STRIDE + col] = hp;
            }
        }
    }

    // ---- q vector: A2 cols 256..319 (first 256 threads; 32 halves each)
    if (tid < 256) {
        int rl = tid >> 1;              // 0..127
        int half = tid & 1;             // cols 256+half*32 .. +31
        int gr = m0 + rl;
        __align__(16) __half qh[32];
#pragma unroll
        for (int i = 0; i < 32; i++) qh[i] = __float2half_rn(0.f);
        if (half == 0 && gr < NE) {
            int cu = g_cnt_ue[gr], cs = g_cnt_se[gr];
            if (cu > 0) {
                float inv = 1.f / (float)cu;
#pragma unroll
                for (int cc = 0; cc < 8; cc++)
                    qh[cc] = __float2half_rn(g_sum8[(size_t)gr * 8 + cc] * inv);
                qh[8] = __float2half_rn(1.f);
            }
            if (cs > 0) {
                qh[9] = __float2half_rn(g_sum1[gr] / (float)cs);
                qh[10] = __float2half_rn(1.f);
            }
        }
#pragma unroll
        for (int u = 0; u < 4; u++)
            *(uint4*)&A2[rl * A2_STRIDE + 256 + half * 32 + u * 8] = ((uint4*)qh)[u];
    }
    __syncthreads();

    // ================= PHASE 2: K = 320, chunks of 64 =================
#pragma unroll
    for (int i = 0; i < 2; i++)
#pragma unroll
        for (int j = 0; j < 4; j++)
#pragma unroll
            for (int q = 0; q < 4; q++) C[i][j][q] = 0.f;

    auto issueB2 = [&](int c, int buf) {
        const int k0 = c * 64;
        uint32_t bh = sbase + (uint32_t)(S0 + buf * STAGE + A_STG) * 2u;
#pragma unroll
        for (int i = 0; i < 2; i++) {
            int f = tid + i * 1024;
            int row = f >> 3, m = f & 7;
            cp16(bh + (uint32_t)(row * ST_ROW + m * 8) * 2,
                 g_WcH + (size_t)row * KB2 + k0 + m * 8);
        }
        CP_COMMIT();
    };

    issueB2(0, 0);

    for (int kt = 0; kt < NC2; kt++) {
        const int cur = kt & 1;
        CP_WAIT0();
        __syncthreads();
        if (kt + 1 < NC2) issueB2(kt + 1, cur ^ 1);

        const uint32_t sBh = sbase + (uint32_t)(S0 + cur * STAGE + A_STG) * 2u;
#pragma unroll
        for (int kh = 0; kh < 4; kh++) {
            uint32_t Af[2][4];
#pragma unroll
            for (int mf = 0; mf < 2; mf++) {
                int row = wm * 32 + mf * 16 + a_row_off;
                uint32_t off = (uint32_t)(row * A2_STRIDE + kt * 64 + kh * 16 + a_k_off) * 2;
                ldsm4(sbase + off, Af[mf][0], Af[mf][1], Af[mf][2], Af[mf][3]);
            }
            uint32_t Bf[2][4];
#pragma unroll
            for (int nf = 0; nf < 2; nf++) {
                int row = wn * 32 + nf * 16 + b_row_off;
                uint32_t off = (uint32_t)(row * ST_ROW + kh * 16 + b_k_off) * 2;
                ldsm4(sBh + off, Bf[nf][0], Bf[nf][1], Bf[nf][2], Bf[nf][3]);
            }
#pragma unroll
            for (int mf = 0; mf < 2; mf++) {
#pragma unroll
                for (int j = 0; j < 4; j++) {
                    int nf = j >> 1;
                    int hh = j & 1;
                    mma16816(C[mf][j], Af[mf], Bf[nf][hh * 2], Bf[nf][hh * 2 + 1]);
                }
            }
        }
    }

    // ---- epilogue 2: bias2, 0.5x, leaky, gated residual -> he in C regs
    const float alpha = 1.f / (1.f + expf(-gate[0]));
#pragma unroll
    for (int mf = 0; mf < 2; mf++) {
        int rl0 = wm * 32 + mf * 16 + g;
#pragma unroll
        for (int j = 0; j < 4; j++) {
            int col = wn * 32 + j * 8 + t * 2;
            float b0 = g_bias2[col], b1 = g_bias2[col + 1];
#pragma unroll
            for (int half = 0; half < 2; half++) {
                int rl = rl0 + half * 8;
                float v0 = C[mf][j][half * 2 + 0] + b0;
                float v1 = C[mf][j][half * 2 + 1] + b1;
                __half2 rh = *(const __half2*)&A2[rl * A2_STRIDE + col];
                float u;
                u = 0.5f * v0; u = u > 0.f ? u : 0.2f * u;
                C[mf][j][half * 2 + 0] = alpha * u + (1.f - alpha) * __half2float(rh.x);
                u = 0.5f * v1; u = u > 0.f ? u : 0.2f * u;
                C[mf][j][half * 2 + 1] = alpha * u + (1.f - alpha) * __half2float(rh.y);
            }
        }
    }
    __syncthreads();   // residual reads done before fp32 he overwrites region

    // ---- he fp32 -> SMEM (aliases A2+stage0; 128x256 floats)
    float* hem = (float*)dsm;
#pragma unroll
    for (int mf = 0; mf < 2; mf++) {
        int rl0 = wm * 32 + mf * 16 + g;
#pragma unroll
        for (int j = 0; j < 4; j++) {
            int col = wn * 32 + j * 8 + t * 2;
#pragma unroll
            for (int half = 0; half < 2; half++) {
                int rl = rl0 + half * 8;
                *(float2*)&hem[rl * 256 + col] =
                    make_float2(C[mf][j][half * 2 + 0], C[mf][j][half * 2 + 1]);
            }
        }
    }
    __syncthreads();

    // ================= PHASE 3: KAN =================
    const float* sbw = kanw;
    const float* ssw = kanw + 512;
    const float c6 = 1.f / 6.f;
#pragma unroll
    for (int rr = 0; rr < 4; rr++) {
        int rl = warp * 4 + rr;
        int row = m0 + rl;
        if (row >= NE) continue;
        float acc0 = 0.f, acc1 = 0.f;
#pragma unroll
        for (int it = 0; it < 8; it++) {
            int h = it * 32 + lane;
            float x = hem[rl * 256 + h];
            float sil = x * __fdividef(1.f, 1.f + __expf(-x));
            acc0 += sil * sbw[h];
            acc1 += sil * sbw[256 + h];
            float tt = (x + 2.2f) * 2.5f;
            float fj = floorf(tt);
            int j = (int)fj;
            if (j >= 0 && j < 11) {
                float u = tt - fj;
                float u2 = u * u, u3 = u2 * u;
                float p0 = u3 * c6;
                float p1 = (1.f + 3.f * (u + u2) - 3.f * u3) * c6;
                float p2 = (4.f - 6.f * u2 + 3.f * u3) * c6;
                float om = 1.f - u;
                float p3 = om * om * om * c6;
                if (j < 8) {
                    acc0 += p0 * ssw[j * 512 + h];
                    acc1 += p0 * ssw[j * 512 + 256 + h];
                }
                int g1 = j - 1;
                if (g1 >= 0 && g1 < 8) {
                    acc0 += p1 * ssw[g1 * 512 + h];
                    acc1 += p1 * ssw[g1 * 512 + 256 + h];
                }
                int g2 = j - 2;
                if (g2 >= 0 && g2 < 8) {
                    acc0 += p2 * ssw[g2 * 512 + h];
                    acc1 += p2 * ssw[g2 * 512 + 256 + h];
                }
                int g3 = j - 3;
                if (g3 >= 0) {
                    acc0 += p3 * ssw[g3 * 512 + h];
                    acc1 += p3 * ssw[g3 * 512 + 256 + h];
                }
            }
        }
#pragma unroll
        for (int off = 16; off; off >>= 1) {
            acc0 += __shfl_xor_sync(0xffffffff, acc0, off);
            acc1 += __shfl_xor_sync(0xffffffff, acc1, off);
        }
        if (lane == 0) {
            out[row * 2 + 0] = acc0;
            out[row * 2 + 1] = acc1;
        }
    }
}

// ---------------- launch ----------------------------------------------------
extern "C" void kernel_launch(void* const* d_in, const int* in_sizes, int n_in,
                              void* d_out, int out_size) {
    const float* x_email   = (const float*)d_in[0];
    const float* x_url     = (const float*)d_in[1];
    const float* x_sender  = (const float*)d_in[2];
    const float* W_e       = (const float*)d_in[3];
    const float* b_e       = (const float*)d_in[4];
    const float* W_u       = (const float*)d_in[5];
    const float* b_u       = (const float*)d_in[6];
    const float* W_s       = (const float*)d_in[7];
    const float* b_s       = (const float*)d_in[8];
    const float* Wl_ue     = (const float*)d_in[12];
    const float* bl_ue     = (const float*)d_in[13];
    const float* Wr_ue     = (const float*)d_in[14];
    const float* Wl_se     = (const float*)d_in[15];
    const float* bl_se     = (const float*)d_in[16];
    const float* Wr_se     = (const float*)d_in[17];
    const float* gate      = (const float*)d_in[21];
    const float* kan_base  = (const float*)d_in[22];
    const float* kan_spline= (const float*)d_in[23];
    const int*   ue_src    = (const int*)d_in[26];
    const int*   ue_dst    = (const int*)d_in[27];
    const int*   se_src    = (const int*)d_in[28];
    const int*   se_dst    = (const int*)d_in[29];
    int n_ue = in_sizes[26];
    int n_se = in_sizes[28];
    float* out = (float*)d_out;

    cudaFuncSetAttribute((void*)fused_gemm, cudaFuncAttributeMaxDynamicSharedMemorySize,
                         SMEM_BYTES);

    prep_kernel<<<KD, 256>>>(W_e, Wr_ue, Wr_se, bl_ue, bl_se);
    prep2_kernel<<<HD, 64>>>(Wl_ue, W_u, b_u, Wl_se, W_s, b_s);
    agg_kernel<<<(n_ue + n_se + 255) / 256, 256>>>(ue_src, ue_dst, x_url, n_ue,
                                                   se_src, se_dst, x_sender, n_se);
    fused_gemm<<<(NE + 127) / 128, 1024, SMEM_BYTES>>>(x_email, b_e, gate,
                                                       kan_base, kan_spline, out);
}

// round 15
// speedup vs baseline: 1.2146x; 1.2146x over previous
#include <cuda_runtime.h>
#include <cuda_fp16.h>
#include <stdint.h>
#include <math.h>

#define NE 50000
#define HD 256
#define KD 768
#define KB1 288   // phase-2 K: 256 he + 32 q (11 real + pad)

// SMEM layout (halves)
#define A2_STRIDE 296                            // 592 B row stride: conflict-free ldsm
#define A2_HALVES (128 * A2_STRIDE)              // 37888
#define S0 A2_HALVES                             // phase-1 staging base (halves)
#define P1_STAGE 15360                           // Ah(5120) + Bh(10240)
#define S0P2 (S0 + 2 * P1_STAGE)                 // 68608: phase-2 staging base
#define P2_STAGE 10240                           // Bh only
#define KAN_OFF (S0P2 + 2 * P2_STAGE)            // 89088 halves = 178176 B
#define KAN_FLOATS 4608                          // sbw 512 + ssw 4096
#define SMEM_BYTES (KAN_OFF * 2 + KAN_FLOATS * 4)  // 196608

// ---------------- scratch ----------------------------------------------------
__device__ __half g_WeH[HD * KD];          // W_e fp16 [n][k] k<768
__device__ __half g_WcH[HD * KB1];         // W' fp16 [n][k] k<288
__device__ float g_bias2[HD];              // bl_ue + bl_se
__device__ float g_sum8[NE * 8];
__device__ float g_sum1[NE];
__device__ int   g_cnt_ue[NE];
__device__ int   g_cnt_se[NE];

// ---------------- zero accumulators (every graph replay) --------------------
__global__ void zero_kernel() {
    int i = blockIdx.x * blockDim.x + threadIdx.x;
    int stride = gridDim.x * blockDim.x;
    for (int j = i; j < NE * 8; j += stride) g_sum8[j] = 0.f;
    for (int j = i; j < NE; j += stride) { g_sum1[j] = 0.f; g_cnt_ue[j] = 0; g_cnt_se[j] = 0; }
}

// ---------------- merged prep + prep2 + agg (disjoint writes) ---------------
__global__ void prep_all(const float* __restrict__ W_e,
                         const float* __restrict__ Wr_ue, const float* __restrict__ Wr_se,
                         const float* __restrict__ bl_ue, const float* __restrict__ bl_se,
                         const float* __restrict__ Wl_ue, const float* __restrict__ W_u,
                         const float* __restrict__ b_u,
                         const float* __restrict__ Wl_se, const float* __restrict__ W_s,
                         const float* __restrict__ b_s,
                         const int* __restrict__ ue_src, const int* __restrict__ ue_dst,
                         const float* __restrict__ x_url, int n_ue,
                         const int* __restrict__ se_src, const int* __restrict__ se_dst,
                         const float* __restrict__ x_sender, int n_se) {
    int b = blockIdx.x;
    int tid = threadIdx.x;
    if (b < 768) {
        // ---- prep: W_e convert, combined Wr, bias2 ----
        int idx = b * 256 + tid;
        if (idx < HD) g_bias2[idx] = bl_ue[idx] + bl_se[idx];
        g_WeH[idx] = __float2half_rn(W_e[idx]);
        if (idx < HD * HD) {
            int n = idx >> 8, k = idx & 255;
            g_WcH[n * KB1 + k] = __float2half_rn(Wr_ue[idx] + Wr_se[idx]);
        }
    } else if (b < 1024) {
        // ---- prep2: rank-11 correction columns ----
        int n = b - 768;
        int c = tid;
        if (c < 32) {
            float acc = 0.f;
            if (c < 8) {
                for (int h = 0; h < HD; h++) acc += Wl_ue[n * HD + h] * W_u[h * 8 + c];
            } else if (c == 8) {
                for (int h = 0; h < HD; h++) acc += Wl_ue[n * HD + h] * b_u[h];
            } else if (c == 9) {
                for (int h = 0; h < HD; h++) acc += Wl_se[n * HD + h] * W_s[h];
            } else if (c == 10) {
                for (int h = 0; h < HD; h++) acc += Wl_se[n * HD + h] * b_s[h];
            }
            g_WcH[n * KB1 + 256 + c] = __float2half_rn(acc);
        }
    } else {
        // ---- agg: edge aggregation (zeroed by zero_kernel beforehand) ----
        int e = (b - 1024) * 256 + tid;
        if (e < n_ue) {
            int s = ue_src[e], d = ue_dst[e];
            const float4* xu = (const float4*)(x_url + (size_t)s * 8);
            float4 a = xu[0], bb = xu[1];
            float* p = g_sum8 + (size_t)d * 8;
            asm volatile("red.global.add.v4.f32 [%0], {%1,%2,%3,%4};"
                         :: "l"(p), "f"(a.x), "f"(a.y), "f"(a.z), "f"(a.w) : "memory");
            asm volatile("red.global.add.v4.f32 [%0], {%1,%2,%3,%4};"
                         :: "l"(p + 4), "f"(bb.x), "f"(bb.y), "f"(bb.z), "f"(bb.w) : "memory");
            asm volatile("red.global.add.s32 [%0], %1;" :: "l"(g_cnt_ue + d), "r"(1) : "memory");
        } else {
            int e2 = e - n_ue;
            if (e2 < n_se) {
                int d = se_dst[e2];
                float v = x_sender[se_src[e2]];
                asm volatile("red.global.add.f32 [%0], %1;" :: "l"(g_sum1 + d), "f"(v) : "memory");
                asm volatile("red.global.add.s32 [%0], %1;" :: "l"(g_cnt_se + d), "r"(1) : "memory");
            }
        }
    }
}

// ---------------- helpers -----------------------------------------------------
__device__ __forceinline__ void cp16(uint32_t d, const void* s) {
    asm volatile("cp.async.cg.shared.global [%0], [%1], 16;" :: "r"(d), "l"(s));
}
#define CP_COMMIT() asm volatile("cp.async.commit_group;")
#define CP_WAIT0()  asm volatile("cp.async.wait_group 0;")

__device__ __forceinline__ void ldsm4(uint32_t addr, uint32_t& r0, uint32_t& r1,
                                      uint32_t& r2, uint32_t& r3) {
    asm volatile("ldmatrix.sync.aligned.m8n8.x4.shared.b16 {%0,%1,%2,%3}, [%4];"
                 : "=r"(r0), "=r"(r1), "=r"(r2), "=r"(r3) : "r"(addr));
}

__device__ __forceinline__ void mma16816(float* c, const uint32_t* a, uint32_t b0, uint32_t b1) {
    asm volatile("mma.sync.aligned.m16n8k16.row.col.f32.f16.f16.f32 "
                 "{%0,%1,%2,%3}, {%4,%5,%6,%7}, {%8,%9}, {%0,%1,%2,%3};"
                 : "+f"(c[0]), "+f"(c[1]), "+f"(c[2]), "+f"(c[3])
                 : "r"(a[0]), "r"(a[1]), "r"(a[2]), "r"(a[3]), "r"(b0), "r"(b1));
}

// ---------------- fully fused: proj + conv + activation + KAN ---------------
// 1024 threads, 32 warps (4m x 8n), warp tile 32x32, block tile 128x256 (r11 config).
__global__ __launch_bounds__(1024, 1) void fused_gemm(const float* __restrict__ x_email,
                                                      const float* __restrict__ b_e,
                                                      const float* __restrict__ gate,
                                                      const float* __restrict__ base_w,
                                                      const float* __restrict__ spline_w,
                                                      float* __restrict__ out) {
    extern __shared__ __half dsm[];
    const uint32_t sbase = (uint32_t)__cvta_generic_to_shared(dsm);
    __half* A2 = dsm;
    float* kanw = (float*)(dsm + KAN_OFF);

    const int tid = threadIdx.x;
    const int lane = tid & 31;
    const int warp = tid >> 5;      // 0..31
    const int wm = warp & 3;        // 4 m-slabs of 32
    const int wn = warp >> 2;       // 8 n-slabs of 32
    const int m0 = blockIdx.x * 128;

    const int a_row_off = ((lane >> 3) & 1) * 8 + (lane & 7);
    const int a_k_off   = ((lane >> 4) & 1) * 8;
    const int b_row_off = ((lane >> 4) & 1) * 8 + (lane & 7);
    const int b_k_off   = ((lane >> 3) & 1) * 8;
    const int g = lane >> 2, t = lane & 3;

    // ---- KAN weight load ----
    for (int i = tid; i < 512; i += 1024) kanw[i] = base_w[i];
    for (int i = tid; i < 4096; i += 1024) {
        int o = i >> 11;
        int h = (i >> 3) & 255;
        int gg = i & 7;
        kanw[512 + gg * 512 + o * 256 + h] = spline_w[i];
    }

    float C[2][4][4];
#pragma unroll
    for (int i = 0; i < 2; i++)
#pragma unroll
        for (int j = 0; j < 4; j++)
#pragma unroll
            for (int q = 0; q < 4; q++) C[i][j][q] = 0.f;

    float4 Ar;

    auto issueB2 = [&](int kt, int buf) {
        const int k0 = kt * 32;
        uint32_t bh = sbase + (uint32_t)(S0P2 + buf * P2_STAGE) * 2u;
        int row = tid >> 2, m = tid & 3;
        cp16(bh + (uint32_t)(row * 40 + m * 8) * 2,
             g_WcH + (size_t)row * KB1 + k0 + m * 8);
        CP_COMMIT();
    };

    // ================= PHASE 1: K = 768, chunks of 32 =================
    auto issueB1 = [&](int kt, int buf) {
        const int k0 = kt * 32;
        uint32_t bh = sbase + (uint32_t)(S0 + buf * P1_STAGE + 5120) * 2u;
        int row = tid >> 2, m = tid & 3;   // 256 rows x 4 chunks
        cp16(bh + (uint32_t)(row * 40 + m * 8) * 2,
             g_WeH + (size_t)row * KD + k0 + m * 8);
        CP_COMMIT();
    };
    auto loadA1 = [&](int kt) {
        const int k0 = kt * 32;
        int row = tid >> 3, c4 = (tid & 7) << 2;  // 128 rows x 8 float4
        int gr = m0 + row;
        Ar = (gr < NE) ? *(const float4*)(x_email + (size_t)gr * KD + k0 + c4)
                       : make_float4(0.f, 0.f, 0.f, 0.f);
    };
    auto storeA1 = [&](int buf) {
        __half* Ah = dsm + S0 + buf * P1_STAGE;
        int row = tid >> 3, c4 = (tid & 7) << 2;
        __half2 hp0; hp0.x = __float2half_rn(Ar.x); hp0.y = __float2half_rn(Ar.y);
        __half2 hp1; hp1.x = __float2half_rn(Ar.z); hp1.y = __float2half_rn(Ar.w);
        *(__half2*)(Ah + row * 40 + c4)     = hp0;
        *(__half2*)(Ah + row * 40 + c4 + 2) = hp1;
    };

    loadA1(0);
    issueB1(0, 0);

    for (int kt = 0; kt < 24; kt++) {
        const int cur = kt & 1;
        storeA1(cur);
        CP_WAIT0();
        __syncthreads();
        if (kt + 1 < 24) {
            issueB1(kt + 1, cur ^ 1);
            loadA1(kt + 1);
        } else {
            issueB2(0, 0);   // cross-phase prefetch: phase-2 B stage 0 (disjoint region)
        }
        const uint32_t sAh = sbase + (uint32_t)(S0 + cur * P1_STAGE) * 2u;
        const uint32_t sBh = sbase + (uint32_t)(S0 + cur * P1_STAGE + 5120) * 2u;
#pragma unroll
        for (int kh = 0; kh < 2; kh++) {
            uint32_t Af[2][4];
#pragma unroll
            for (int mf = 0; mf < 2; mf++) {
                int row = wm * 32 + mf * 16 + a_row_off;
                uint32_t off = (uint32_t)(row * 40 + kh * 16 + a_k_off) * 2;
                ldsm4(sAh + off, Af[mf][0], Af[mf][1], Af[mf][2], Af[mf][3]);
            }
            uint32_t Bf[2][4];
#pragma unroll
            for (int nf = 0; nf < 2; nf++) {
                int row = wn * 32 + nf * 16 + b_row_off;
                uint32_t off = (uint32_t)(row * 40 + kh * 16 + b_k_off) * 2;
                ldsm4(sBh + off, Bf[nf][0], Bf[nf][1], Bf[nf][2], Bf[nf][3]);
            }
#pragma unroll
            for (int mf = 0; mf < 2; mf++) {
#pragma unroll
                for (int j = 0; j < 4; j++) {
                    int nf = j >> 1;
                    int hh = j & 1;
                    mma16816(C[mf][j], Af[mf], Bf[nf][hh * 2], Bf[nf][hh * 2 + 1]);
                }
            }
        }
    }

    // ---- epilogue 1: he_pre + b_e -> fp16 A2 cols 0..255
#pragma unroll
    for (int mf = 0; mf < 2; mf++) {
        int rl0 = wm * 32 + mf * 16 + g;
#pragma unroll
        for (int j = 0; j < 4; j++) {
            int col = wn * 32 + j * 8 + t * 2;
            float b0 = b_e[col], b1 = b_e[col + 1];
#pragma unroll
            for (int half = 0; half < 2; half++) {
                int rl = rl0 + half * 8;
                __half2 hp;
                hp.x = __float2half_rn(C[mf][j][half * 2 + 0] + b0);
                hp.y = __float2half_rn(C[mf][j][half * 2 + 1] + b1);
                *(__half2*)&A2[rl * A2_STRIDE + col] = hp;
            }
        }
    }

    // ---- q vector: A2 cols 256..287 (8 threads per row, 4 cols each)
    {
        int rl = tid >> 3;
        int cc = (tid & 7) * 4;
        int gr = m0 + rl;
        float qv[4];
#pragma unroll
        for (int i = 0; i < 4; i++) qv[i] = 0.f;
        if (gr < NE && cc < 12) {
            int cu = g_cnt_ue[gr];
            int cs = g_cnt_se[gr];
            float invu = (cu > 0) ? 1.f / (float)cu : 0.f;
#pragma unroll
            for (int i = 0; i < 4; i++) {
                int qi = cc + i;
                float v = 0.f;
                if (qi < 8)       v = g_sum8[(size_t)gr * 8 + qi] * invu;
                else if (qi == 8)  v = (cu > 0) ? 1.f : 0.f;
                else if (qi == 9)  v = (cs > 0) ? g_sum1[gr] / (float)cs : 0.f;
                else if (qi == 10) v = (cs > 0) ? 1.f : 0.f;
                qv[i] = v;
            }
        }
        __half2 hp0; hp0.x = __float2half_rn(qv[0]); hp0.y = __float2half_rn(qv[1]);
        __half2 hp1; hp1.x = __float2half_rn(qv[2]); hp1.y = __float2half_rn(qv[3]);
        *(__half2*)&A2[rl * A2_STRIDE + 256 + cc]     = hp0;
        *(__half2*)&A2[rl * A2_STRIDE + 256 + cc + 2] = hp1;
    }
    __syncthreads();

    // ================= PHASE 2: K = 288, fp16-hi weights =================
#pragma unroll
    for (int i = 0; i < 2; i++)
#pragma unroll
        for (int j = 0; j < 4; j++)
#pragma unroll
            for (int q = 0; q < 4; q++) C[i][j][q] = 0.f;

    for (int kt = 0; kt < 9; kt++) {
        const int cur = kt & 1;
        CP_WAIT0();
        __syncthreads();
        if (kt + 1 < 9) issueB2(kt + 1, cur ^ 1);

        const uint32_t sBh = sbase + (uint32_t)(S0P2 + cur * P2_STAGE) * 2u;
#pragma unroll
        for (int kh = 0; kh < 2; kh++) {
            uint32_t Af[2][4];
#pragma unroll
            for (int mf = 0; mf < 2; mf++) {
                int row = wm * 32 + mf * 16 + a_row_off;
                uint32_t off = (uint32_t)(row * A2_STRIDE + kt * 32 + kh * 16 + a_k_off) * 2;
                ldsm4(sbase + off, Af[mf][0], Af[mf][1], Af[mf][2], Af[mf][3]);
            }
            uint32_t Bf[2][4];
#pragma unroll
            for (int nf = 0; nf < 2; nf++) {
                int row = wn * 32 + nf * 16 + b_row_off;
                uint32_t off = (uint32_t)(row * 40 + kh * 16 + b_k_off) * 2;
                ldsm4(sBh + off, Bf[nf][0], Bf[nf][1], Bf[nf][2], Bf[nf][3]);
            }
#pragma unroll
            for (int mf = 0; mf < 2; mf++) {
#pragma unroll
                for (int j = 0; j < 4; j++) {
                    int nf = j >> 1;
                    int hh = j & 1;
                    mma16816(C[mf][j], Af[mf], Bf[nf][hh * 2], Bf[nf][hh * 2 + 1]);
                }
            }
        }
    }

    // ---- epilogue 2: bias2, 0.5x, leaky, gated residual -> he in C regs
    const float alpha = 1.f / (1.f + expf(-gate[0]));
#pragma unroll
    for (int mf = 0; mf < 2; mf++) {
        int rl0 = wm * 32 + mf * 16 + g;
#pragma unroll
        for (int j = 0; j < 4; j++) {
            int col = wn * 32 + j * 8 + t * 2;
            float b0 = g_bias2[col], b1 = g_bias2[col + 1];
#pragma unroll
            for (int half = 0; half < 2; half++) {
                int rl = rl0 + half * 8;
                float v0 = C[mf][j][half * 2 + 0] + b0;
                float v1 = C[mf][j][half * 2 + 1] + b1;
                __half2 rh = *(const __half2*)&A2[rl * A2_STRIDE + col];
                float u;
                u = 0.5f * v0; u = u > 0.f ? u : 0.2f * u;
                C[mf][j][half * 2 + 0] = alpha * u + (1.f - alpha) * __half2float(rh.x);
                u = 0.5f * v1; u = u > 0.f ? u : 0.2f * u;
                C[mf][j][half * 2 + 1] = alpha * u + (1.f - alpha) * __half2float(rh.y);
            }
        }
    }
    __syncthreads();   // residual reads complete before fp32 he overwrites region

    // ---- he fp32 -> SMEM (aliases A2+staging; 128x256 floats)
    float* hem = (float*)dsm;
#pragma unroll
    for (int mf = 0; mf < 2; mf++) {
        int rl0 = wm * 32 + mf * 16 + g;
#pragma unroll
        for (int j = 0; j < 4; j++) {
            int col = wn * 32 + j * 8 + t * 2;
#pragma unroll
            for (int half = 0; half < 2; half++) {
                int rl = rl0 + half * 8;
                *(float2*)&hem[rl * 256 + col] =
                    make_float2(C[mf][j][half * 2 + 0], C[mf][j][half * 2 + 1]);
            }
        }
    }
    __syncthreads();

    // ================= PHASE 3: KAN =================
    const float* sbw = kanw;
    const float* ssw = kanw + 512;
    const float c6 = 1.f / 6.f;
#pragma unroll
    for (int rr = 0; rr < 4; rr++) {
        int rl = warp * 4 + rr;
        int row = m0 + rl;
        if (row >= NE) continue;
        float acc0 = 0.f, acc1 = 0.f;
#pragma unroll
        for (int it = 0; it < 8; it++) {
            int h = it * 32 + lane;
            float x = hem[rl * 256 + h];
            float sil = x * __fdividef(1.f, 1.f + __expf(-x));
            acc0 += sil * sbw[h];
            acc1 += sil * sbw[256 + h];
            float tt = (x + 2.2f) * 2.5f;
            float fj = floorf(tt);
            int j = (int)fj;
            if (j >= 0 && j < 11) {
                float u = tt - fj;
                float u2 = u * u, u3 = u2 * u;
                float p0 = u3 * c6;
                float p1 = (1.f + 3.f * (u + u2) - 3.f * u3) * c6;
                float p2 = (4.f - 6.f * u2 + 3.f * u3) * c6;
                float om = 1.f - u;
                float p3 = om * om * om * c6;
                if (j < 8) {
                    acc0 += p0 * ssw[j * 512 + h];
                    acc1 += p0 * ssw[j * 512 + 256 + h];
                }
                int g1 = j - 1;
                if (g1 >= 0 && g1 < 8) {
                    acc0 += p1 * ssw[g1 * 512 + h];
                    acc1 += p1 * ssw[g1 * 512 + 256 + h];
                }
                int g2 = j - 2;
                if (g2 >= 0 && g2 < 8) {
                    acc0 += p2 * ssw[g2 * 512 + h];
                    acc1 += p2 * ssw[g2 * 512 + 256 + h];
                }
                int g3 = j - 3;
                if (g3 >= 0) {
                    acc0 += p3 * ssw[g3 * 512 + h];
                    acc1 += p3 * ssw[g3 * 512 + 256 + h];
                }
            }
        }
#pragma unroll
        for (int off = 16; off; off >>= 1) {
            acc0 += __shfl_xor_sync(0xffffffff, acc0, off);
            acc1 += __shfl_xor_sync(0xffffffff, acc1, off);
        }
        if (lane == 0) {
            out[row * 2 + 0] = acc0;
            out[row * 2 + 1] = acc1;
        }
    }
}

// ---------------- launch ----------------------------------------------------
extern "C" void kernel_launch(void* const* d_in, const int* in_sizes, int n_in,
                              void* d_out, int out_size) {
    const float* x_email   = (const float*)d_in[0];
    const float* x_url     = (const float*)d_in[1];
    const float* x_sender  = (const float*)d_in[2];
    const float* W_e       = (const float*)d_in[3];
    const float* b_e       = (const float*)d_in[4];
    const float* W_u       = (const float*)d_in[5];
    const float* b_u       = (const float*)d_in[6];
    const float* W_s       = (const float*)d_in[7];
    const float* b_s       = (const float*)d_in[8];
    const float* Wl_ue     = (const float*)d_in[12];
    const float* bl_ue     = (const float*)d_in[13];
    const float* Wr_ue     = (const float*)d_in[14];
    const float* Wl_se     = (const float*)d_in[15];
    const float* bl_se     = (const float*)d_in[16];
    const float* Wr_se     = (const float*)d_in[17];
    const float* gate      = (const float*)d_in[21];
    const float* kan_base  = (const float*)d_in[22];
    const float* kan_spline= (const float*)d_in[23];
    const int*   ue_src    = (const int*)d_in[26];
    const int*   ue_dst    = (const int*)d_in[27];
    const int*   se_src    = (const int*)d_in[28];
    const int*   se_dst    = (const int*)d_in[29];
    int n_ue = in_sizes[26];
    int n_se = in_sizes[28];
    float* out = (float*)d_out;

    cudaFuncSetAttribute((void*)fused_gemm, cudaFuncAttributeMaxDynamicSharedMemorySize,
                         SMEM_BYTES);

    int n_agg_blocks = (n_ue + n_se + 255) / 256;
    zero_kernel<<<512, 256>>>();
    prep_all<<<1024 + n_agg_blocks, 256>>>(W_e, Wr_ue, Wr_se, bl_ue, bl_se,
                                           Wl_ue, W_u, b_u, Wl_se, W_s, b_s,
                                           ue_src, ue_dst, x_url, n_ue,
                                           se_src, se_dst, x_sender, n_se);
    fused_gemm<<<(NE + 127) / 128, 1024, SMEM_BYTES>>>(x_email, b_e, gate,
                                                       kan_base, kan_spline, out);
}